// round 16
// baseline (speedup 1.0000x reference)
#include <cuda_runtime.h>
#include <cuda_bf16.h>
#include <cstdint>
#include <cstddef>

// Problem constants
#define BB 4
#define CC 128
#define NN 4096      // H*W
#define CQ 16
#define TQ 128       // queries per CTA
#define TK 128       // keys per tile
#define NTILES (NN / TK)   // 32
#define LOG2E 1.44269504088896340736f

// ---------------------------------------------------------------------------
// Device scratch
// g_qb/g_kb: bf16 [b][n][cq]   (q pre-scaled by log2 e)
// g_vb: bf16 [b][c][n]
// ---------------------------------------------------------------------------
__device__ __align__(16) __nv_bfloat16 g_qb[(size_t)BB * NN * CQ];
__device__ __align__(16) __nv_bfloat16 g_kb[(size_t)BB * NN * CQ];
__device__ __align__(16) __nv_bfloat16 g_vb[(size_t)BB * CC * NN];

// ---------------------------------------------------------------------------
// Helpers
// ---------------------------------------------------------------------------
__device__ __forceinline__ uint32_t smem_u32(const void* p) {
    uint32_t a;
    asm("{ .reg .u64 t; cvta.to.shared.u64 t, %1; cvt.u32.u64 %0, t; }"
        : "=r"(a) : "l"(p));
    return a;
}
// pack two fp32 -> bf16x2 (lo in low half)
__device__ __forceinline__ uint32_t pack_bf2(float lo, float hi) {
    uint32_t r;
    asm("cvt.rn.satfinite.bf16x2.f32 %0, %1, %2;" : "=r"(r) : "f"(hi), "f"(lo));
    return r;
}
__device__ __forceinline__ float ex2f(float x) {
    float y;
    asm("ex2.approx.f32 %0, %1;" : "=f"(y) : "f"(x));
    return y;
}
__device__ __forceinline__ void cp16(uint32_t dst, const void* src) {
    asm volatile("cp.async.cg.shared.global [%0], [%1], 16;"
                 :: "r"(dst), "l"(src));
}
#define CP_COMMIT() asm volatile("cp.async.commit_group;" ::: "memory")
#define CP_WAIT(n)  asm volatile("cp.async.wait_group %0;" :: "n"(n) : "memory")

// mma.m16n8k16 bf16 -> fp32
__device__ __forceinline__ void mma16816(
    float* d,
    uint32_t a0, uint32_t a1, uint32_t a2, uint32_t a3,
    uint32_t b0, uint32_t b1,
    float c0, float c1, float c2, float c3)
{
    asm volatile(
        "mma.sync.aligned.m16n8k16.row.col.f32.bf16.bf16.f32 "
        "{%0,%1,%2,%3}, {%4,%5,%6,%7}, {%8,%9}, {%10,%11,%12,%13};"
        : "=f"(d[0]), "=f"(d[1]), "=f"(d[2]), "=f"(d[3])
        : "r"(a0), "r"(a1), "r"(a2), "r"(a3),
          "r"(b0), "r"(b1),
          "f"(c0), "f"(c1), "f"(c2), "f"(c3));
}

// ---------------------------------------------------------------------------
// Kernel 1: QKV HMMA GEMM with fused fp32->bf16 transpose of x. (R15)
// ---------------------------------------------------------------------------
#define QKP 272
#define XFP 132
#define SM_W  0
#define SM_XT 43520
#define SM_XF (SM_XT + 34816)
#define XF_BYTES (32 * XFP * 4)
#define QKV_SMEM (SM_XF + 2 * XF_BYTES)

__global__ void __launch_bounds__(256, 1) qkv_kernel(
    const float* __restrict__ x,
    const float* __restrict__ wq, const float* __restrict__ bq,
    const float* __restrict__ wk, const float* __restrict__ bk,
    const float* __restrict__ wv, const float* __restrict__ bv)
{
    extern __shared__ char sm[];
    const uint32_t smb = smem_u32(sm);
    const int tid  = threadIdx.x;
    const int w    = tid >> 5;
    const int lane = tid & 31;
    const int p    = lane >> 2;
    const int q    = lane & 3;

    const int b  = blockIdx.y;
    const int n0 = blockIdx.x * 128;
    const float* xb = x + (size_t)b * CC * NN + n0;

#pragma unroll
    for (int kc = 0; kc < 2; ++kc) {
        const uint32_t dst = smb + SM_XF + kc * XF_BYTES;
#pragma unroll
        for (int it = 0; it < 4; ++it) {
            const int i = tid + it * 256;
            const int r = i >> 5, cc = i & 31;
            cp16(dst + (uint32_t)(r * XFP + cc * 4) * 4,
                 xb + (size_t)(kc * 32 + r) * NN + cc * 4);
        }
        CP_COMMIT();
    }

    for (int i = tid; i < 160 * 64; i += 256) {
        const int m  = i >> 6;
        const int k2 = (i & 63) * 2;
        float v0, v1;
        if (m < 16) {
            const float2 t = *(const float2*)(wq + m * CC + k2);
            v0 = t.x * LOG2E; v1 = t.y * LOG2E;
        } else if (m < 32) {
            const float2 t = *(const float2*)(wk + (m - 16) * CC + k2);
            v0 = t.x; v1 = t.y;
        } else {
            const float2 t = *(const float2*)(wv + (m - 32) * CC + k2);
            v0 = t.x; v1 = t.y;
        }
        *(uint32_t*)(sm + SM_W + m * QKP + k2 * 2) = pack_bf2(v0, v1);
    }

#pragma unroll
    for (int kc = 0; kc < 4; ++kc) {
        if (kc < 2) { CP_WAIT(1); } else { CP_WAIT(0); }
        __syncthreads();

        const float* xf = (const float*)(sm + SM_XF + (kc & 1) * XF_BYTES);
#pragma unroll
        for (int it = 0; it < 8; ++it) {
            const int i  = tid + it * 256;
            const int kp = i >> 7;
            const int n  = i & 127;
            const uint32_t u = pack_bf2(xf[(2 * kp) * XFP + n],
                                        xf[(2 * kp + 1) * XFP + n]);
            *(uint32_t*)(sm + SM_XT + n * QKP + kc * 64 + kp * 4) = u;
        }
        __syncthreads();

        if (kc + 2 < 4) {
            const uint32_t dst = smb + SM_XF + (kc & 1) * XF_BYTES;
#pragma unroll
            for (int it = 0; it < 4; ++it) {
                const int i = tid + it * 256;
                const int r = i >> 5, cc = i & 31;
                cp16(dst + (uint32_t)(r * XFP + cc * 4) * 4,
                     xb + (size_t)((kc + 2) * 32 + r) * NN + cc * 4);
            }
            CP_COMMIT();
        }
    }

    float o[10][8];
#pragma unroll
    for (int mt = 0; mt < 10; ++mt)
#pragma unroll
        for (int k = 0; k < 8; ++k) o[mt][k] = 0.f;

    const char* Wb = sm + SM_W;
    const char* Xb = sm + SM_XT;
#pragma unroll
    for (int ks = 0; ks < 8; ++ks) {
        const int ko = 32 * ks + 4 * q;
        const char* br0 = Xb + (16 * w + p)     * QKP + ko;
        const char* br1 = Xb + (16 * w + 8 + p) * QKP + ko;
        const uint32_t bka0 = *(const uint32_t*)(br0);
        const uint32_t bka1 = *(const uint32_t*)(br0 + 16);
        const uint32_t bkb0 = *(const uint32_t*)(br1);
        const uint32_t bkb1 = *(const uint32_t*)(br1 + 16);
#pragma unroll
        for (int mt = 0; mt < 10; ++mt) {
            const char* ar0 = Wb + (mt * 16 + p)     * QKP + ko;
            const char* ar1 = Wb + (mt * 16 + 8 + p) * QKP + ko;
            const uint32_t a0 = *(const uint32_t*)(ar0);
            const uint32_t a1 = *(const uint32_t*)(ar1);
            const uint32_t a2 = *(const uint32_t*)(ar0 + 16);
            const uint32_t a3 = *(const uint32_t*)(ar1 + 16);
            mma16816(o[mt],     a0, a1, a2, a3, bka0, bka1,
                     o[mt][0], o[mt][1], o[mt][2], o[mt][3]);
            mma16816(o[mt] + 4, a0, a1, a2, a3, bkb0, bkb1,
                     o[mt][4], o[mt][5], o[mt][6], o[mt][7]);
        }
    }
    __syncthreads();

    const int ncol = n0 + 16 * w + 2 * q;
#pragma unroll
    for (int mt = 2; mt < 10; ++mt) {
        const int cm0 = mt * 16 + p - 32;
        const int cm1 = cm0 + 8;
        const float b0 = __ldg(bv + cm0);
        const float b1 = __ldg(bv + cm1);
        char* base0 = (char*)g_vb + (((size_t)b * CC + cm0) * NN + ncol) * 2;
        char* base1 = (char*)g_vb + (((size_t)b * CC + cm1) * NN + ncol) * 2;
        *(uint32_t*)(base0)      = pack_bf2(o[mt][0] + b0, o[mt][1] + b0);
        *(uint32_t*)(base1)      = pack_bf2(o[mt][2] + b1, o[mt][3] + b1);
        *(uint32_t*)(base0 + 16) = pack_bf2(o[mt][4] + b0, o[mt][5] + b0);
        *(uint32_t*)(base1 + 16) = pack_bf2(o[mt][6] + b1, o[mt][7] + b1);
    }

    float* ts = (float*)(sm + SM_XT);
#pragma unroll
    for (int mt = 0; mt < 2; ++mt) {
        const int m0r = mt * 16 + p;
        const int m1r = m0r + 8;
        const float bb0 = (mt == 0) ? __ldg(bq + m0r) * LOG2E : __ldg(bk + m0r - 16);
        const float bb1 = (mt == 0) ? __ldg(bq + m1r) * LOG2E : __ldg(bk + m1r - 16);
        const int c0 = 16 * w + 2 * q;
        ts[m0r * 133 + c0]     = o[mt][0] + bb0;
        ts[m0r * 133 + c0 + 1] = o[mt][1] + bb0;
        ts[m1r * 133 + c0]     = o[mt][2] + bb1;
        ts[m1r * 133 + c0 + 1] = o[mt][3] + bb1;
        ts[m0r * 133 + c0 + 8] = o[mt][4] + bb0;
        ts[m0r * 133 + c0 + 9] = o[mt][5] + bb0;
        ts[m1r * 133 + c0 + 8] = o[mt][6] + bb1;
        ts[m1r * 133 + c0 + 9] = o[mt][7] + bb1;
    }
    __syncthreads();

    {
        const int half = tid >> 7;
        const int nl   = tid & 127;
        const int rb   = half * 16;
        uint32_t pk[8];
#pragma unroll
        for (int j = 0; j < 8; ++j)
            pk[j] = pack_bf2(ts[(rb + 2 * j) * 133 + nl],
                             ts[(rb + 2 * j + 1) * 133 + nl]);
        char* dst = (char*)(half ? g_kb : g_qb) + ((size_t)b * NN + n0 + nl) * 32;
        *(uint4*)(dst)      = make_uint4(pk[0], pk[1], pk[2], pk[3]);
        *(uint4*)(dst + 16) = make_uint4(pk[4], pk[5], pk[6], pk[7]);
    }
}

// ---------------------------------------------------------------------------
// Kernel 2: HMMA flash attention — depth-2 software pipeline:
// MMA1 runs 2 steps ahead, exp 1 step ahead, so each iteration's MUFU block
// (exp of s+1) is independent of its HMMA block (MMA2 of s) and they
// interleave in the issue stream.
// ---------------------------------------------------------------------------
#define KPITCH 48
#define VPITCH 272
#define SM_Q   0
#define SM_K0  6144
#define SM_K1  12288
#define SM_V0  18432
#define SM_V1  (SM_V0 + 34816)
#define SM_TOTAL (SM_V1 + 34816)

__device__ __forceinline__ void issue_tile(
    uint32_t smb, const char* kg, const char* vg, int t, int buf, int tid)
{
    const uint32_t kdst = smb + (buf ? SM_K1 : SM_K0);
    const uint32_t vdst = smb + (buf ? SM_V1 : SM_V0);
    const int m0 = t * TK;
    {
        const int n = tid >> 1, h = tid & 1;
        cp16(kdst + n * KPITCH + h * 16, kg + (size_t)(m0 + n) * 32 + h * 16);
    }
#pragma unroll
    for (int it = 0; it < 8; ++it) {
        const int i = tid + it * 256;
        const int c = i >> 4, h = i & 15;
        cp16(vdst + c * VPITCH + h * 16,
             vg + (size_t)c * (NN * 2) + (size_t)m0 * 2 + h * 16);
    }
}

// MMA1 for s-step s from K smem
__device__ __forceinline__ void mma1_step(
    float* d, const char* smK, int s, int p, int q,
    uint32_t qa0, uint32_t qa1, uint32_t qa2, uint32_t qa3)
{
    const char* kr0 = smK + (16 * s + p)     * KPITCH + 4 * q;
    const char* kr1 = smK + (16 * s + 8 + p) * KPITCH + 4 * q;
    const uint32_t bka0 = *(const uint32_t*)(kr0);
    const uint32_t bka1 = *(const uint32_t*)(kr0 + 16);
    const uint32_t bkb0 = *(const uint32_t*)(kr1);
    const uint32_t bkb1 = *(const uint32_t*)(kr1 + 16);
    mma16816(d,     qa0, qa1, qa2, qa3, bka0, bka1, 0.f, 0.f, 0.f, 0.f);
    mma16816(d + 4, qa0, qa1, qa2, qa3, bkb0, bkb1, 0.f, 0.f, 0.f, 0.f);
}

__global__ void __launch_bounds__(256, 1) attn_kernel(
    const float* __restrict__ x,
    const float* __restrict__ gamma,
    float* __restrict__ out)
{
    extern __shared__ char sm[];
    const uint32_t smb = smem_u32(sm);
    const int tid  = threadIdx.x;
    const int w    = tid >> 5;
    const int lane = tid & 31;
    const int p    = lane >> 2;
    const int q    = lane & 3;

    const int b  = blockIdx.y;
    const int n0 = blockIdx.x * TQ;

    const char* qg = (const char*)g_qb + ((size_t)b * NN + n0) * 32;
    const char* kg = (const char*)g_kb + (size_t)b * NN * 32;
    const char* vg = (const char*)g_vb + (size_t)b * CC * NN * 2;

    {
        const int r = tid >> 1, h = tid & 1;
        *(uint4*)(sm + SM_Q + r * KPITCH + h * 16) =
            *(const uint4*)(qg + r * 32 + h * 16);
    }
    issue_tile(smb, kg, vg, 0, 0, tid);
    CP_COMMIT();
    __syncthreads();

    uint32_t qa0, qa1, qa2, qa3;
    {
        const int r = 16 * w + p;
        qa0 = *(const uint32_t*)(sm + SM_Q + r       * KPITCH + 4 * q);
        qa1 = *(const uint32_t*)(sm + SM_Q + (r + 8) * KPITCH + 4 * q);
        qa2 = *(const uint32_t*)(sm + SM_Q + r       * KPITCH + 16 + 4 * q);
        qa3 = *(const uint32_t*)(sm + SM_Q + (r + 8) * KPITCH + 16 + 4 * q);
    }

    float o[16][4];
#pragma unroll
    for (int jc = 0; jc < 16; ++jc)
#pragma unroll
        for (int k = 0; k < 4; ++k) o[jc][k] = 0.f;
    float l0 = 0.f, l1 = 0.f;

    for (int t = 0; t < NTILES; ++t) {
        if (t + 1 < NTILES) {
            issue_tile(smb, kg, vg, t + 1, (t + 1) & 1, tid);
            CP_COMMIT();
            CP_WAIT(1);
        } else {
            CP_WAIT(0);
        }
        __syncthreads();

        const char* smK = sm + ((t & 1) ? SM_K1 : SM_K0);
        const char* smV = sm + ((t & 1) ? SM_V1 : SM_V0);

        // ---- prologue: MMA1(0), MMA1(1), exp(0) ----
        float db[8];          // scores of step s+1
        uint32_t pa0, pa1, pa2, pa3;   // P of step s
        {
            float da[8];
            mma1_step(da, smK, 0, p, q, qa0, qa1, qa2, qa3);
            mma1_step(db, smK, 1, p, q, qa0, qa1, qa2, qa3);
            const float e0 = ex2f(da[0]), e1 = ex2f(da[1]);
            const float e2 = ex2f(da[2]), e3 = ex2f(da[3]);
            const float e4 = ex2f(da[4]), e5 = ex2f(da[5]);
            const float e6 = ex2f(da[6]), e7 = ex2f(da[7]);
            l0 += (e0 + e1) + (e4 + e5);
            l1 += (e2 + e3) + (e6 + e7);
            pa0 = pack_bf2(e0, e1); pa1 = pack_bf2(e2, e3);
            pa2 = pack_bf2(e4, e5); pa3 = pack_bf2(e6, e7);
        }

#pragma unroll
        for (int s = 0; s < 8; ++s) {
            // ---- MMA1(s+2) ----
            float dn[8];
            if (s + 2 < 8)
                mma1_step(dn, smK, s + 2, p, q, qa0, qa1, qa2, qa3);

            // ---- exp(s+1): db was issued a full iteration ago ----
            uint32_t pn0, pn1, pn2, pn3;
            if (s + 1 < 8) {
                const float e0 = ex2f(db[0]), e1 = ex2f(db[1]);
                const float e2 = ex2f(db[2]), e3 = ex2f(db[3]);
                const float e4 = ex2f(db[4]), e5 = ex2f(db[5]);
                const float e6 = ex2f(db[6]), e7 = ex2f(db[7]);
                l0 += (e0 + e1) + (e4 + e5);
                l1 += (e2 + e3) + (e6 + e7);
                pn0 = pack_bf2(e0, e1); pn1 = pack_bf2(e2, e3);
                pn2 = pack_bf2(e4, e5); pn3 = pack_bf2(e6, e7);
            }

            // ---- MMA2(s): independent of the exp block above ----
#pragma unroll
            for (int jc = 0; jc < 16; ++jc) {
                const char* vr = smV + (8 * jc + p) * VPITCH + 32 * s + 4 * q;
                const uint32_t bv0 = *(const uint32_t*)(vr);
                const uint32_t bv1 = *(const uint32_t*)(vr + 16);
                mma16816(o[jc], pa0, pa1, pa2, pa3, bv0, bv1,
                         o[jc][0], o[jc][1], o[jc][2], o[jc][3]);
            }

            // ---- rotate pipeline ----
            pa0 = pn0; pa1 = pn1; pa2 = pn2; pa3 = pn3;
#pragma unroll
            for (int k = 0; k < 8; ++k) db[k] = dn[k];
        }
        __syncthreads();
    }

    l0 += __shfl_xor_sync(0xffffffffu, l0, 1);
    l0 += __shfl_xor_sync(0xffffffffu, l0, 2);
    l1 += __shfl_xor_sync(0xffffffffu, l1, 1);
    l1 += __shfl_xor_sync(0xffffffffu, l1, 2);
    const float inv0 = 1.f / l0;
    const float inv1 = 1.f / l1;

    const float g = __ldg(gamma);
    const int nrow = n0 + 16 * w + p;
#pragma unroll
    for (int jc = 0; jc < 16; ++jc) {
        const int c = 8 * jc + 2 * q;
        const size_t i0 = ((size_t)b * CC + c) * NN + nrow;
        out[i0]          = g * (o[jc][0] * inv0) + x[i0];
        out[i0 + NN]     = g * (o[jc][1] * inv0) + x[i0 + NN];
        out[i0 + 8]      = g * (o[jc][2] * inv1) + x[i0 + 8];
        out[i0 + NN + 8] = g * (o[jc][3] * inv1) + x[i0 + NN + 8];
    }
}

// ---------------------------------------------------------------------------
// Launch
// ---------------------------------------------------------------------------
extern "C" void kernel_launch(void* const* d_in, const int* in_sizes, int n_in,
                              void* d_out, int out_size)
{
    const float* x     = (const float*)d_in[0];
    const float* wq    = (const float*)d_in[1];
    const float* bq    = (const float*)d_in[2];
    const float* wk    = (const float*)d_in[3];
    const float* bk    = (const float*)d_in[4];
    const float* wv    = (const float*)d_in[5];
    const float* bv    = (const float*)d_in[6];
    const float* gamma = (const float*)d_in[7];
    float* out = (float*)d_out;
    (void)in_sizes; (void)n_in; (void)out_size;

    cudaFuncSetAttribute(qkv_kernel,
                         cudaFuncAttributeMaxDynamicSharedMemorySize, QKV_SMEM);
    qkv_kernel<<<dim3(NN / 128, BB), 256, QKV_SMEM>>>(x, wq, bq, wk, bk, wv, bv);

    cudaFuncSetAttribute(attn_kernel,
                         cudaFuncAttributeMaxDynamicSharedMemorySize, SM_TOTAL);
    attn_kernel<<<dim3(NN / TQ, BB), 256, SM_TOTAL>>>(x, gamma, out);
}

// round 17
// speedup vs baseline: 1.0457x; 1.0457x over previous
#include <cuda_runtime.h>
#include <cuda_bf16.h>
#include <cstdint>
#include <cstddef>

// Problem constants
#define BB 4
#define CC 128
#define NN 4096      // H*W
#define CQ 16
#define TQ 128       // queries per CTA
#define TK 128       // keys per tile
#define NTILES (NN / TK)   // 32
#define LOG2E 1.44269504088896340736f

// ---------------------------------------------------------------------------
// Device scratch
// g_qb/g_kb: bf16 [b][n][cq]   (q pre-scaled by log2 e)
// g_vb: bf16 [b][c][n]
// ---------------------------------------------------------------------------
__device__ __align__(16) __nv_bfloat16 g_qb[(size_t)BB * NN * CQ];
__device__ __align__(16) __nv_bfloat16 g_kb[(size_t)BB * NN * CQ];
__device__ __align__(16) __nv_bfloat16 g_vb[(size_t)BB * CC * NN];

// ---------------------------------------------------------------------------
// Helpers
// ---------------------------------------------------------------------------
__device__ __forceinline__ uint32_t smem_u32(const void* p) {
    uint32_t a;
    asm("{ .reg .u64 t; cvta.to.shared.u64 t, %1; cvt.u32.u64 %0, t; }"
        : "=r"(a) : "l"(p));
    return a;
}
// pack two fp32 -> bf16x2 (lo in low half)
__device__ __forceinline__ uint32_t pack_bf2(float lo, float hi) {
    uint32_t r;
    asm("cvt.rn.satfinite.bf16x2.f32 %0, %1, %2;" : "=r"(r) : "f"(hi), "f"(lo));
    return r;
}
__device__ __forceinline__ float ex2f(float x) {
    float y;
    asm("ex2.approx.f32 %0, %1;" : "=f"(y) : "f"(x));
    return y;
}
__device__ __forceinline__ void cp16(uint32_t dst, const void* src) {
    asm volatile("cp.async.cg.shared.global [%0], [%1], 16;"
                 :: "r"(dst), "l"(src));
}
#define CP_COMMIT() asm volatile("cp.async.commit_group;" ::: "memory")
#define CP_WAIT(n)  asm volatile("cp.async.wait_group %0;" :: "n"(n) : "memory")

// mma.m16n8k16 bf16 -> fp32
__device__ __forceinline__ void mma16816(
    float* d,
    uint32_t a0, uint32_t a1, uint32_t a2, uint32_t a3,
    uint32_t b0, uint32_t b1,
    float c0, float c1, float c2, float c3)
{
    asm volatile(
        "mma.sync.aligned.m16n8k16.row.col.f32.bf16.bf16.f32 "
        "{%0,%1,%2,%3}, {%4,%5,%6,%7}, {%8,%9}, {%10,%11,%12,%13};"
        : "=f"(d[0]), "=f"(d[1]), "=f"(d[2]), "=f"(d[3])
        : "r"(a0), "r"(a1), "r"(a2), "r"(a3),
          "r"(b0), "r"(b1),
          "f"(c0), "f"(c1), "f"(c2), "f"(c3));
}
// ldmatrix x4: four 8x8 b16 matrices, row addrs from 32 lanes
__device__ __forceinline__ void ldsm4(
    uint32_t& r0, uint32_t& r1, uint32_t& r2, uint32_t& r3, uint32_t addr)
{
    asm volatile(
        "ldmatrix.sync.aligned.m8n8.x4.shared.b16 {%0,%1,%2,%3}, [%4];"
        : "=r"(r0), "=r"(r1), "=r"(r2), "=r"(r3) : "r"(addr));
}

// ---------------------------------------------------------------------------
// Kernel 1: QKV HMMA GEMM with fused fp32->bf16 transpose of x. (R15)
// ---------------------------------------------------------------------------
#define QKP 272
#define XFP 132
#define SM_W  0
#define SM_XT 43520
#define SM_XF (SM_XT + 34816)
#define XF_BYTES (32 * XFP * 4)
#define QKV_SMEM (SM_XF + 2 * XF_BYTES)

__global__ void __launch_bounds__(256, 1) qkv_kernel(
    const float* __restrict__ x,
    const float* __restrict__ wq, const float* __restrict__ bq,
    const float* __restrict__ wk, const float* __restrict__ bk,
    const float* __restrict__ wv, const float* __restrict__ bv)
{
    extern __shared__ char sm[];
    const uint32_t smb = smem_u32(sm);
    const int tid  = threadIdx.x;
    const int w    = tid >> 5;
    const int lane = tid & 31;
    const int p    = lane >> 2;
    const int q    = lane & 3;

    const int b  = blockIdx.y;
    const int n0 = blockIdx.x * 128;
    const float* xb = x + (size_t)b * CC * NN + n0;

#pragma unroll
    for (int kc = 0; kc < 2; ++kc) {
        const uint32_t dst = smb + SM_XF + kc * XF_BYTES;
#pragma unroll
        for (int it = 0; it < 4; ++it) {
            const int i = tid + it * 256;
            const int r = i >> 5, cc = i & 31;
            cp16(dst + (uint32_t)(r * XFP + cc * 4) * 4,
                 xb + (size_t)(kc * 32 + r) * NN + cc * 4);
        }
        CP_COMMIT();
    }

    for (int i = tid; i < 160 * 64; i += 256) {
        const int m  = i >> 6;
        const int k2 = (i & 63) * 2;
        float v0, v1;
        if (m < 16) {
            const float2 t = *(const float2*)(wq + m * CC + k2);
            v0 = t.x * LOG2E; v1 = t.y * LOG2E;
        } else if (m < 32) {
            const float2 t = *(const float2*)(wk + (m - 16) * CC + k2);
            v0 = t.x; v1 = t.y;
        } else {
            const float2 t = *(const float2*)(wv + (m - 32) * CC + k2);
            v0 = t.x; v1 = t.y;
        }
        *(uint32_t*)(sm + SM_W + m * QKP + k2 * 2) = pack_bf2(v0, v1);
    }

#pragma unroll
    for (int kc = 0; kc < 4; ++kc) {
        if (kc < 2) { CP_WAIT(1); } else { CP_WAIT(0); }
        __syncthreads();

        const float* xf = (const float*)(sm + SM_XF + (kc & 1) * XF_BYTES);
#pragma unroll
        for (int it = 0; it < 8; ++it) {
            const int i  = tid + it * 256;
            const int kp = i >> 7;
            const int n  = i & 127;
            const uint32_t u = pack_bf2(xf[(2 * kp) * XFP + n],
                                        xf[(2 * kp + 1) * XFP + n]);
            *(uint32_t*)(sm + SM_XT + n * QKP + kc * 64 + kp * 4) = u;
        }
        __syncthreads();

        if (kc + 2 < 4) {
            const uint32_t dst = smb + SM_XF + (kc & 1) * XF_BYTES;
#pragma unroll
            for (int it = 0; it < 4; ++it) {
                const int i = tid + it * 256;
                const int r = i >> 5, cc = i & 31;
                cp16(dst + (uint32_t)(r * XFP + cc * 4) * 4,
                     xb + (size_t)((kc + 2) * 32 + r) * NN + cc * 4);
            }
            CP_COMMIT();
        }
    }

    float o[10][8];
#pragma unroll
    for (int mt = 0; mt < 10; ++mt)
#pragma unroll
        for (int k = 0; k < 8; ++k) o[mt][k] = 0.f;

    const char* Wb = sm + SM_W;
    const char* Xb = sm + SM_XT;
#pragma unroll
    for (int ks = 0; ks < 8; ++ks) {
        const int ko = 32 * ks + 4 * q;
        const char* br0 = Xb + (16 * w + p)     * QKP + ko;
        const char* br1 = Xb + (16 * w + 8 + p) * QKP + ko;
        const uint32_t bka0 = *(const uint32_t*)(br0);
        const uint32_t bka1 = *(const uint32_t*)(br0 + 16);
        const uint32_t bkb0 = *(const uint32_t*)(br1);
        const uint32_t bkb1 = *(const uint32_t*)(br1 + 16);
#pragma unroll
        for (int mt = 0; mt < 10; ++mt) {
            const char* ar0 = Wb + (mt * 16 + p)     * QKP + ko;
            const char* ar1 = Wb + (mt * 16 + 8 + p) * QKP + ko;
            const uint32_t a0 = *(const uint32_t*)(ar0);
            const uint32_t a1 = *(const uint32_t*)(ar1);
            const uint32_t a2 = *(const uint32_t*)(ar0 + 16);
            const uint32_t a3 = *(const uint32_t*)(ar1 + 16);
            mma16816(o[mt],     a0, a1, a2, a3, bka0, bka1,
                     o[mt][0], o[mt][1], o[mt][2], o[mt][3]);
            mma16816(o[mt] + 4, a0, a1, a2, a3, bkb0, bkb1,
                     o[mt][4], o[mt][5], o[mt][6], o[mt][7]);
        }
    }
    __syncthreads();

    const int ncol = n0 + 16 * w + 2 * q;
#pragma unroll
    for (int mt = 2; mt < 10; ++mt) {
        const int cm0 = mt * 16 + p - 32;
        const int cm1 = cm0 + 8;
        const float b0 = __ldg(bv + cm0);
        const float b1 = __ldg(bv + cm1);
        char* base0 = (char*)g_vb + (((size_t)b * CC + cm0) * NN + ncol) * 2;
        char* base1 = (char*)g_vb + (((size_t)b * CC + cm1) * NN + ncol) * 2;
        *(uint32_t*)(base0)      = pack_bf2(o[mt][0] + b0, o[mt][1] + b0);
        *(uint32_t*)(base1)      = pack_bf2(o[mt][2] + b1, o[mt][3] + b1);
        *(uint32_t*)(base0 + 16) = pack_bf2(o[mt][4] + b0, o[mt][5] + b0);
        *(uint32_t*)(base1 + 16) = pack_bf2(o[mt][6] + b1, o[mt][7] + b1);
    }

    float* ts = (float*)(sm + SM_XT);
#pragma unroll
    for (int mt = 0; mt < 2; ++mt) {
        const int m0r = mt * 16 + p;
        const int m1r = m0r + 8;
        const float bb0 = (mt == 0) ? __ldg(bq + m0r) * LOG2E : __ldg(bk + m0r - 16);
        const float bb1 = (mt == 0) ? __ldg(bq + m1r) * LOG2E : __ldg(bk + m1r - 16);
        const int c0 = 16 * w + 2 * q;
        ts[m0r * 133 + c0]     = o[mt][0] + bb0;
        ts[m0r * 133 + c0 + 1] = o[mt][1] + bb0;
        ts[m1r * 133 + c0]     = o[mt][2] + bb1;
        ts[m1r * 133 + c0 + 1] = o[mt][3] + bb1;
        ts[m0r * 133 + c0 + 8] = o[mt][4] + bb0;
        ts[m0r * 133 + c0 + 9] = o[mt][5] + bb0;
        ts[m1r * 133 + c0 + 8] = o[mt][6] + bb1;
        ts[m1r * 133 + c0 + 9] = o[mt][7] + bb1;
    }
    __syncthreads();

    {
        const int half = tid >> 7;
        const int nl   = tid & 127;
        const int rb   = half * 16;
        uint32_t pk[8];
#pragma unroll
        for (int j = 0; j < 8; ++j)
            pk[j] = pack_bf2(ts[(rb + 2 * j) * 133 + nl],
                             ts[(rb + 2 * j + 1) * 133 + nl]);
        char* dst = (char*)(half ? g_kb : g_qb) + ((size_t)b * NN + n0 + nl) * 32;
        *(uint4*)(dst)      = make_uint4(pk[0], pk[1], pk[2], pk[3]);
        *(uint4*)(dst + 16) = make_uint4(pk[4], pk[5], pk[6], pk[7]);
    }
}

// ---------------------------------------------------------------------------
// Kernel 2: HMMA flash attention (R13 pipeline) + ldmatrix.x4 for V fragments.
// One LDSM.x4 feeds TWO MMA2s (matrices: [ch 16jp..+7 | 16jp+8..+15] x
// [k-half 0 | 1]); per s-step 32 LDS.32 -> 8 LDSM, 4x fewer scoreboard events.
// smem: Q [128][48] 6144 | K0/K1 6144 | V0/V1 [128c][272] 34816 ea. 88064 B.
// ---------------------------------------------------------------------------
#define KPITCH 48
#define VPITCH 272
#define SM_Q   0
#define SM_K0  6144
#define SM_K1  12288
#define SM_V0  18432
#define SM_V1  (SM_V0 + 34816)
#define SM_TOTAL (SM_V1 + 34816)

__device__ __forceinline__ void issue_tile(
    uint32_t smb, const char* kg, const char* vg, int t, int buf, int tid)
{
    const uint32_t kdst = smb + (buf ? SM_K1 : SM_K0);
    const uint32_t vdst = smb + (buf ? SM_V1 : SM_V0);
    const int m0 = t * TK;
    {
        const int n = tid >> 1, h = tid & 1;
        cp16(kdst + n * KPITCH + h * 16, kg + (size_t)(m0 + n) * 32 + h * 16);
    }
#pragma unroll
    for (int it = 0; it < 8; ++it) {
        const int i = tid + it * 256;
        const int c = i >> 4, h = i & 15;
        cp16(vdst + c * VPITCH + h * 16,
             vg + (size_t)c * (NN * 2) + (size_t)m0 * 2 + h * 16);
    }
}

__global__ void __launch_bounds__(256, 1) attn_kernel(
    const float* __restrict__ x,
    const float* __restrict__ gamma,
    float* __restrict__ out)
{
    extern __shared__ char sm[];
    const uint32_t smb = smem_u32(sm);
    const int tid  = threadIdx.x;
    const int w    = tid >> 5;
    const int lane = tid & 31;
    const int p    = lane >> 2;
    const int q    = lane & 3;

    const int b  = blockIdx.y;
    const int n0 = blockIdx.x * TQ;

    const char* qg = (const char*)g_qb + ((size_t)b * NN + n0) * 32;
    const char* kg = (const char*)g_kb + (size_t)b * NN * 32;
    const char* vg = (const char*)g_vb + (size_t)b * CC * NN * 2;

    {
        const int r = tid >> 1, h = tid & 1;
        *(uint4*)(sm + SM_Q + r * KPITCH + h * 16) =
            *(const uint4*)(qg + r * 32 + h * 16);
    }
    issue_tile(smb, kg, vg, 0, 0, tid);
    CP_COMMIT();
    __syncthreads();

    uint32_t qa0, qa1, qa2, qa3;
    {
        const int r = 16 * w + p;
        qa0 = *(const uint32_t*)(sm + SM_Q + r       * KPITCH + 4 * q);
        qa1 = *(const uint32_t*)(sm + SM_Q + (r + 8) * KPITCH + 4 * q);
        qa2 = *(const uint32_t*)(sm + SM_Q + r       * KPITCH + 16 + 4 * q);
        qa3 = *(const uint32_t*)(sm + SM_Q + (r + 8) * KPITCH + 16 + 4 * q);
    }

    // per-lane ldmatrix row offset: channel row (lane&7) + 8*(lane>=16),
    // byte column 16*((lane>>3)&1)  [k-half selector]
    const uint32_t vlane_off =
        (uint32_t)(((lane & 7) + ((lane >> 4) << 3)) * VPITCH +
                   (((lane >> 3) & 1) << 4));

    float o[16][4];
#pragma unroll
    for (int jc = 0; jc < 16; ++jc)
#pragma unroll
        for (int k = 0; k < 4; ++k) o[jc][k] = 0.f;
    float l0 = 0.f, l1 = 0.f;

    for (int t = 0; t < NTILES; ++t) {
        if (t + 1 < NTILES) {
            issue_tile(smb, kg, vg, t + 1, (t + 1) & 1, tid);
            CP_COMMIT();
            CP_WAIT(1);
        } else {
            CP_WAIT(0);
        }
        __syncthreads();

        const char* smK = sm + ((t & 1) ? SM_K1 : SM_K0);
        const uint32_t smV = smb + ((t & 1) ? SM_V1 : SM_V0) + vlane_off;

        float d[8];
        {
            const char* kr0 = smK + p * KPITCH + 4 * q;
            const char* kr1 = smK + (8 + p) * KPITCH + 4 * q;
            const uint32_t bka0 = *(const uint32_t*)(kr0);
            const uint32_t bka1 = *(const uint32_t*)(kr0 + 16);
            const uint32_t bkb0 = *(const uint32_t*)(kr1);
            const uint32_t bkb1 = *(const uint32_t*)(kr1 + 16);
            mma16816(d,     qa0, qa1, qa2, qa3, bka0, bka1, 0.f, 0.f, 0.f, 0.f);
            mma16816(d + 4, qa0, qa1, qa2, qa3, bkb0, bkb1, 0.f, 0.f, 0.f, 0.f);
        }

#pragma unroll
        for (int s = 0; s < 8; ++s) {
            float dn[8];
            if (s < 7) {
                const char* kr0 = smK + (16 * (s + 1) + p)     * KPITCH + 4 * q;
                const char* kr1 = smK + (16 * (s + 1) + 8 + p) * KPITCH + 4 * q;
                const uint32_t bka0 = *(const uint32_t*)(kr0);
                const uint32_t bka1 = *(const uint32_t*)(kr0 + 16);
                const uint32_t bkb0 = *(const uint32_t*)(kr1);
                const uint32_t bkb1 = *(const uint32_t*)(kr1 + 16);
                mma16816(dn,     qa0, qa1, qa2, qa3, bka0, bka1, 0.f, 0.f, 0.f, 0.f);
                mma16816(dn + 4, qa0, qa1, qa2, qa3, bkb0, bkb1, 0.f, 0.f, 0.f, 0.f);
            }

            const float e0 = ex2f(d[0]), e1 = ex2f(d[1]);
            const float e2 = ex2f(d[2]), e3 = ex2f(d[3]);
            const float e4 = ex2f(d[4]), e5 = ex2f(d[5]);
            const float e6 = ex2f(d[6]), e7 = ex2f(d[7]);
            l0 += (e0 + e1) + (e4 + e5);
            l1 += (e2 + e3) + (e6 + e7);

            const uint32_t pa0 = pack_bf2(e0, e1);
            const uint32_t pa1 = pack_bf2(e2, e3);
            const uint32_t pa2 = pack_bf2(e4, e5);
            const uint32_t pa3 = pack_bf2(e6, e7);

            // ---- MMA2 via ldmatrix: 8 LDSM.x4, each feeding 2 MMAs ----
            const uint32_t vs = smV + 32 * s;
#pragma unroll
            for (int jp = 0; jp < 8; ++jp) {
                uint32_t b00, b01, b10, b11;
                ldsm4(b00, b01, b10, b11,
                      vs + (uint32_t)(jp * 16 * VPITCH));
                float* oa = o[2 * jp];
                float* ob = o[2 * jp + 1];
                mma16816(oa, pa0, pa1, pa2, pa3, b00, b01,
                         oa[0], oa[1], oa[2], oa[3]);
                mma16816(ob, pa0, pa1, pa2, pa3, b10, b11,
                         ob[0], ob[1], ob[2], ob[3]);
            }

#pragma unroll
            for (int k = 0; k < 8; ++k) d[k] = dn[k];
        }
        __syncthreads();
    }

    l0 += __shfl_xor_sync(0xffffffffu, l0, 1);
    l0 += __shfl_xor_sync(0xffffffffu, l0, 2);
    l1 += __shfl_xor_sync(0xffffffffu, l1, 1);
    l1 += __shfl_xor_sync(0xffffffffu, l1, 2);
    const float inv0 = 1.f / l0;
    const float inv1 = 1.f / l1;

    const float g = __ldg(gamma);
    const int nrow = n0 + 16 * w + p;
#pragma unroll
    for (int jc = 0; jc < 16; ++jc) {
        const int c = 8 * jc + 2 * q;
        const size_t i0 = ((size_t)b * CC + c) * NN + nrow;
        out[i0]          = g * (o[jc][0] * inv0) + x[i0];
        out[i0 + NN]     = g * (o[jc][1] * inv0) + x[i0 + NN];
        out[i0 + 8]      = g * (o[jc][2] * inv1) + x[i0 + 8];
        out[i0 + NN + 8] = g * (o[jc][3] * inv1) + x[i0 + NN + 8];
    }
}

// ---------------------------------------------------------------------------
// Launch
// ---------------------------------------------------------------------------
extern "C" void kernel_launch(void* const* d_in, const int* in_sizes, int n_in,
                              void* d_out, int out_size)
{
    const float* x     = (const float*)d_in[0];
    const float* wq    = (const float*)d_in[1];
    const float* bq    = (const float*)d_in[2];
    const float* wk    = (const float*)d_in[3];
    const float* bk    = (const float*)d_in[4];
    const float* wv    = (const float*)d_in[5];
    const float* bv    = (const float*)d_in[6];
    const float* gamma = (const float*)d_in[7];
    float* out = (float*)d_out;
    (void)in_sizes; (void)n_in; (void)out_size;

    cudaFuncSetAttribute(qkv_kernel,
                         cudaFuncAttributeMaxDynamicSharedMemorySize, QKV_SMEM);
    qkv_kernel<<<dim3(NN / 128, BB), 256, QKV_SMEM>>>(x, wq, bq, wk, bk, wv, bv);

    cudaFuncSetAttribute(attn_kernel,
                         cudaFuncAttributeMaxDynamicSharedMemorySize, SM_TOTAL);
    attn_kernel<<<dim3(NN / TQ, BB), 256, SM_TOTAL>>>(x, gamma, out);
}